// round 8
// baseline (speedup 1.0000x reference)
#include <cuda_runtime.h>
#include <math.h>
#include <stdint.h>

#define NN 100000
#define RR 3
#define EE 320000
#define HIDD 128
#define HH 4
#define HD 128
#define NTOT (RR * NN)

// ---------------- device scratch ----------------
__device__ float g_hs  [(size_t)RR * NN * HD];
__device__ float g_z   [(size_t)RR * NN * HD];
__device__ float g_el  [(size_t)RR * NN * HH];
__device__ float g_er  [(size_t)RR * NN * HH];
__device__ float g_WcT [RR * HIDD * HD];
__device__ float g_bc  [RR * HD];
__device__ float g_W1T [HD * 128];
__device__ float g_V   [RR * HIDD * HH];
__device__ float g_c   [RR * HH];
__device__ float g_wsum[RR];
__device__ float g_a   [RR];
// CSR scratch
__device__ int g_deg [NTOT];
__device__ int g_off [NTOT];
__device__ int g_cur [NTOT];
__device__ int g_bsum[512];
__device__ int g_srcs[RR * EE];

// ---------------- helpers ----------------
__device__ __forceinline__ float to_tf32(float x) {
    uint32_t o;
    asm("cvt.rna.tf32.f32 %0, %1;" : "=r"(o) : "f"(x));
    return __uint_as_float(o);
}

#define LDSM4(r0, r1, r2, r3, addr) \
    asm volatile("ldmatrix.sync.aligned.m8n8.x4.shared.b16 {%0,%1,%2,%3}, [%4];" \
                 : "=r"(r0), "=r"(r1), "=r"(r2), "=r"(r3) : "r"(addr))

#define MMA_TF32(c, a, b) \
    asm volatile("mma.sync.aligned.m16n8k8.row.col.f32.tf32.tf32.f32 " \
                 "{%0,%1,%2,%3},{%4,%5,%6,%7},{%8,%9},{%0,%1,%2,%3};" \
                 : "+f"((c)[0]), "+f"((c)[1]), "+f"((c)[2]), "+f"((c)[3]) \
                 : "r"((a)[0]), "r"((a)[1]), "r"((a)[2]), "r"((a)[3]), \
                   "r"((b)[0]), "r"((b)[1]))

// ---------------- fused prep ----------------
constexpr int PB_COMBINE = RR * (HIDD + 1);                 // 387
constexpr int PB_W1T     = PB_COMBINE + 128;                // 515
constexpr int PB_UV      = PB_W1T + RR;                     // 518
constexpr int PB_ZERO    = PB_UV + (NTOT / 4 + 127) / 128;  // 1104
constexpr int PB_TOTAL   = PB_ZERO + 1;                     // 1105

__global__ __launch_bounds__(128) void k_prep(
    const float* __restrict__ Wt_src, const float* __restrict__ bt_src,
    const float* __restrict__ Wg, const float* __restrict__ W1,
    const float* __restrict__ attn_r,
    const float* __restrict__ Wt_dst, const float* __restrict__ bt_dst) {
    int b = blockIdx.x;
    int tid = threadIdx.x;
    if (b < PB_COMBINE) {
        int r = b / (HIDD + 1);
        int i = b % (HIDD + 1);
        __shared__ float srow[HIDD];
        const float* Wgr = Wg + (size_t)r * HIDD * HD;
        srow[tid] = (i < HIDD) ? Wt_src[((size_t)r * HIDD + i) * HIDD + tid]
                               : bt_src[r * HIDD + tid];
        __syncthreads();
        float acc = 0.f;
        #pragma unroll 8
        for (int k = 0; k < HIDD; k++) acc += srow[k] * Wgr[k * HD + tid];
        if (i < HIDD) g_WcT[((size_t)r * HIDD + tid) * HIDD + i] = to_tf32(acc);
        else          g_bc[r * HD + tid] = acc;
    } else if (b < PB_W1T) {
        int idx = (b - PB_COMBINE) * 128 + tid;
        int n = idx >> 7, k = idx & 127;
        g_W1T[n * 128 + k] = to_tf32(W1[k * 128 + n]);
    } else if (b < PB_UV) {
        int r = b - PB_W1T;
        __shared__ float su[HIDD * HH];
        const float* wg = Wg + (size_t)r * HIDD * HD + tid * HD;
        const float* ar = attn_r + r * HD;
        #pragma unroll
        for (int h = 0; h < HH; h++) {
            float s = 0.f;
            #pragma unroll
            for (int d = 0; d < 32; d++) s += wg[h * 32 + d] * ar[h * 32 + d];
            su[tid * HH + h] = s;
        }
        __syncthreads();
        const float* wd = Wt_dst + tid * HIDD;
        #pragma unroll
        for (int h = 0; h < HH; h++) {
            float s = 0.f;
            for (int k = 0; k < HIDD; k++) s += wd[k] * su[k * HH + h];
            g_V[r * HIDD * HH + tid * HH + h] = s;
        }
        if (tid < HH) {
            float c = 0.f;
            for (int k = 0; k < HIDD; k++) c += bt_dst[k] * su[k * HH + tid];
            g_c[r * HH + tid] = c;
        }
    } else if (b < PB_ZERO) {
        int i = (b - PB_UV) * 128 + tid;
        if (i < NTOT / 4) ((int4*)g_deg)[i] = make_int4(0, 0, 0, 0);
    } else {
        if (tid < RR) g_wsum[tid] = 0.f;
    }
}

// ---------------- CSR build ----------------
__global__ void k_hist(const int* __restrict__ dst_idx) {
    int idx = blockIdx.x * blockDim.x + threadIdx.x;
    if (idx >= RR * EE) return;
    int r = idx / EE;
    atomicAdd(&g_deg[r * NN + dst_idx[idx]], 1);
}

__global__ void k_scan1() {
    __shared__ int ssum[256];
    int t = threadIdx.x;
    int base = blockIdx.x * 1024 + t * 4;
    int v0 = base + 0 < NTOT ? g_deg[base + 0] : 0;
    int v1 = base + 1 < NTOT ? g_deg[base + 1] : 0;
    int v2 = base + 2 < NTOT ? g_deg[base + 2] : 0;
    int v3 = base + 3 < NTOT ? g_deg[base + 3] : 0;
    int tot = v0 + v1 + v2 + v3;
    ssum[t] = tot;
    __syncthreads();
    for (int o = 1; o < 256; o <<= 1) {
        int x = t >= o ? ssum[t - o] : 0;
        __syncthreads();
        ssum[t] += x;
        __syncthreads();
    }
    int ex = ssum[t] - tot;
    if (t == 255) g_bsum[blockIdx.x] = ssum[255];
    if (base + 0 < NTOT) g_off[base + 0] = ex;
    if (base + 1 < NTOT) g_off[base + 1] = ex + v0;
    if (base + 2 < NTOT) g_off[base + 2] = ex + v0 + v1;
    if (base + 3 < NTOT) g_off[base + 3] = ex + v0 + v1 + v2;
}

__global__ void k_scan2() {
    __shared__ int s[512];
    int t = threadIdx.x;
    const int NB = (NTOT + 1023) / 1024;
    int v = t < NB ? g_bsum[t] : 0;
    s[t] = v;
    __syncthreads();
    for (int o = 1; o < 512; o <<= 1) {
        int x = t >= o ? s[t - o] : 0;
        __syncthreads();
        s[t] += x;
        __syncthreads();
    }
    if (t < NB) g_bsum[t] = s[t] - v;
}

__global__ void k_scan3() {
    int i = blockIdx.x * blockDim.x + threadIdx.x;
    if (i >= NTOT) return;
    int o = g_off[i] + g_bsum[i >> 10];
    g_off[i] = o;
    g_cur[i] = o;
}

__global__ void k_fill(const int* __restrict__ src_idx, const int* __restrict__ dst_idx) {
    int idx = blockIdx.x * blockDim.x + threadIdx.x;
    if (idx >= RR * EE) return;
    int r = idx / EE;
    int pos = atomicAdd(&g_cur[r * NN + dst_idx[idx]], 1);
    g_srcs[pos] = src_idx[idx];
}

// ---------------- TF32 MMA GEMM geometry ----------------
constexpr int AS_STR = 20;
constexpr int WS_STR = 132;
constexpr int AS_BUF = 128 * AS_STR;
constexpr int SMEM_FLOATS = 128 * WS_STR + 2 * AS_BUF;

// ---------------- hs GEMM ----------------
__global__ __launch_bounds__(256) void k_gemm_hs_mma(const float* __restrict__ src_feats,
                                                     const float* __restrict__ attn_l) {
    extern __shared__ float sm[];
    float* Ws = sm;
    float* As = sm + 128 * WS_STR;
    int tid = threadIdx.x;
    int r = blockIdx.y;
    int row0 = blockIdx.x * 128;
    const float* A = src_feats + (size_t)r * NN * HIDD;

    const float4* Wt4 = (const float4*)(g_WcT + (size_t)r * HIDD * HD);
    #pragma unroll
    for (int i = 0; i < 16; i++) {
        int idx = tid + i * 256;
        int n = idx >> 5, kq = idx & 31;
        *(float4*)(Ws + n * WS_STR + kq * 4) = Wt4[idx];
    }

    int grow = row0 + (tid >> 1);
    int koffA = (tid & 1) * 8;
    float4 areg0, areg1;
    float4 z4 = make_float4(0.f, 0.f, 0.f, 0.f);

    uint32_t sbase = (uint32_t)__cvta_generic_to_shared(sm);
    uint32_t asbase = sbase + 128 * WS_STR * 4;

    int lane = tid & 31, warp = tid >> 5;
    int warp_m = warp >> 1, warp_n = warp & 1;
    int n0 = warp_n * 64;
    int g = lane >> 2, tg = lane & 3;
    int grp = lane >> 3, rin = lane & 7;
    int arow = (grp & 1) * 8 + rin;
    int akoff = (grp >> 1) * 4;
    int brow = (grp >> 1) * 8 + rin;
    int bkoff = (grp & 1) * 4;

    uint32_t aAddr[2], bAddr[4];
    #pragma unroll
    for (int mt = 0; mt < 2; mt++)
        aAddr[mt] = asbase + ((warp_m * 32 + mt * 16 + arow) * AS_STR + akoff) * 4;
    #pragma unroll
    for (int pi = 0; pi < 4; pi++)
        bAddr[pi] = sbase + ((n0 + pi * 16 + brow) * WS_STR + bkoff) * 4;

    float c[2][8][4];
    #pragma unroll
    for (int mt = 0; mt < 2; mt++)
        #pragma unroll
        for (int nt = 0; nt < 8; nt++)
            #pragma unroll
            for (int q = 0; q < 4; q++) c[mt][nt][q] = 0.f;

    if (grow < NN) {
        const float4* p = (const float4*)(A + (size_t)grow * HIDD + koffA);
        areg0 = p[0]; areg1 = p[1];
    } else { areg0 = z4; areg1 = z4; }

    for (int kb = 0; kb < 8; kb++) {
        {
            float* dst = As + (kb & 1) * AS_BUF + (tid >> 1) * AS_STR + koffA;
            dst[0] = to_tf32(areg0.x); dst[1] = to_tf32(areg0.y);
            dst[2] = to_tf32(areg0.z); dst[3] = to_tf32(areg0.w);
            dst[4] = to_tf32(areg1.x); dst[5] = to_tf32(areg1.y);
            dst[6] = to_tf32(areg1.z); dst[7] = to_tf32(areg1.w);
        }
        if (kb < 7) {
            if (grow < NN) {
                const float4* p = (const float4*)(A + (size_t)grow * HIDD + (kb + 1) * 16 + koffA);
                areg0 = p[0]; areg1 = p[1];
            } else { areg0 = z4; areg1 = z4; }
        }
        __syncthreads();
        uint32_t abufoff = (kb & 1) * AS_BUF * 4;
        #pragma unroll
        for (int k8 = 0; k8 < 2; k8++) {
            uint32_t a[2][4], b[8][2];
            #pragma unroll
            for (int mt = 0; mt < 2; mt++)
                LDSM4(a[mt][0], a[mt][1], a[mt][2], a[mt][3],
                      aAddr[mt] + abufoff + k8 * 32);
            #pragma unroll
            for (int pi = 0; pi < 4; pi++)
                LDSM4(b[2 * pi][0], b[2 * pi][1], b[2 * pi + 1][0], b[2 * pi + 1][1],
                      bAddr[pi] + (kb * 16 + k8 * 8) * 4);
            #pragma unroll
            for (int mt = 0; mt < 2; mt++)
                #pragma unroll
                for (int nt = 0; nt < 8; nt++)
                    MMA_TF32(c[mt][nt], a[mt], b[nt]);
        }
    }

    float2 bc2[8], al2[8];
    #pragma unroll
    for (int nt = 0; nt < 8; nt++) {
        bc2[nt] = *(const float2*)(g_bc + r * HD + n0 + nt * 8 + 2 * tg);
        al2[nt] = *(const float2*)(attn_l + r * HD + n0 + nt * 8 + 2 * tg);
    }
    float elp[2][2][2];
    #pragma unroll
    for (int mt = 0; mt < 2; mt++)
        #pragma unroll
        for (int rh = 0; rh < 2; rh++) { elp[mt][rh][0] = 0.f; elp[mt][rh][1] = 0.f; }

    #pragma unroll
    for (int mt = 0; mt < 2; mt++) {
        int rowa = row0 + warp_m * 32 + mt * 16 + g;
        #pragma unroll
        for (int nt = 0; nt < 8; nt++) {
            float c0 = c[mt][nt][0] + bc2[nt].x, c1 = c[mt][nt][1] + bc2[nt].y;
            float c2 = c[mt][nt][2] + bc2[nt].x, c3 = c[mt][nt][3] + bc2[nt].y;
            int h = nt >> 2;
            elp[mt][0][h] += c0 * al2[nt].x + c1 * al2[nt].y;
            elp[mt][1][h] += c2 * al2[nt].x + c3 * al2[nt].y;
            if (rowa < NN)
                *(float2*)(g_hs + ((size_t)r * NN + rowa) * HD + n0 + nt * 8 + 2 * tg) = make_float2(c0, c1);
            if (rowa + 8 < NN)
                *(float2*)(g_hs + ((size_t)r * NN + rowa + 8) * HD + n0 + nt * 8 + 2 * tg) = make_float2(c2, c3);
        }
    }
    #pragma unroll
    for (int off = 1; off < 4; off <<= 1)
        #pragma unroll
        for (int mt = 0; mt < 2; mt++)
            #pragma unroll
            for (int rh = 0; rh < 2; rh++) {
                elp[mt][rh][0] += __shfl_xor_sync(0xffffffffu, elp[mt][rh][0], off);
                elp[mt][rh][1] += __shfl_xor_sync(0xffffffffu, elp[mt][rh][1], off);
            }
    if (tg == 0) {
        #pragma unroll
        for (int mt = 0; mt < 2; mt++)
            #pragma unroll
            for (int rh = 0; rh < 2; rh++) {
                int row = row0 + warp_m * 32 + mt * 16 + g + rh * 8;
                if (row < NN) {
                    g_el[((size_t)r * NN + row) * HH + warp_n * 2 + 0] = elp[mt][rh][0];
                    g_el[((size_t)r * NN + row) * HH + warp_n * 2 + 1] = elp[mt][rh][1];
                }
            }
    }
}

// ---------------- er: dst_feat @ V ----------------
__global__ void k_er(const float* __restrict__ dst_feat) {
    __shared__ float sV[RR * HIDD * HH];
    __shared__ float sc[RR * HH];
    int tid = threadIdx.x;
    for (int i = tid; i < RR * HIDD * HH; i += blockDim.x) sV[i] = g_V[i];
    if (tid < RR * HH) sc[tid] = g_c[tid];
    __syncthreads();
    int node = blockIdx.x * 8 + (tid >> 5);
    int lane = tid & 31;
    if (node >= NN) return;
    float4 f = ((const float4*)dst_feat)[(size_t)node * 32 + lane];
    #pragma unroll
    for (int r = 0; r < RR; r++) {
        const float* base = sV + r * HIDD * HH;
        float4 v0 = *(const float4*)(base + (lane * 4 + 0) * 4);
        float4 v1 = *(const float4*)(base + (lane * 4 + 1) * 4);
        float4 v2 = *(const float4*)(base + (lane * 4 + 2) * 4);
        float4 v3 = *(const float4*)(base + (lane * 4 + 3) * 4);
        float p0 = f.x * v0.x + f.y * v1.x + f.z * v2.x + f.w * v3.x;
        float p1 = f.x * v0.y + f.y * v1.y + f.z * v2.y + f.w * v3.y;
        float p2 = f.x * v0.z + f.y * v1.z + f.z * v2.z + f.w * v3.z;
        float p3 = f.x * v0.w + f.y * v1.w + f.z * v2.w + f.w * v3.w;
        #pragma unroll
        for (int off = 16; off; off >>= 1) {
            p0 += __shfl_xor_sync(0xffffffffu, p0, off);
            p1 += __shfl_xor_sync(0xffffffffu, p1, off);
            p2 += __shfl_xor_sync(0xffffffffu, p2, off);
            p3 += __shfl_xor_sync(0xffffffffu, p3, off);
        }
        if (lane == 0) {
            float* erp = g_er + ((size_t)r * NN + node) * HH;
            erp[0] = p0 + sc[r * HH + 0];
            erp[1] = p1 + sc[r * HH + 1];
            erp[2] = p2 + sc[r * HH + 2];
            erp[3] = p3 + sc[r * HH + 3];
        }
    }
}

// ---------------- pull aggregation: warp per (r,dst), MLP-unrolled ----------------
__global__ __launch_bounds__(256) void k_gather(const float* __restrict__ bias_g) {
    int w = (blockIdx.x * 256 + threadIdx.x) >> 5;
    int lane = threadIdx.x & 31;
    if (w >= NTOT) return;
    int r = w / NN;
    int off = g_off[w], deg = g_deg[w];
    int h = lane >> 3;
    float er = g_er[(size_t)w * HH + h];
    float a0 = 0.f, a1 = 0.f, a2 = 0.f, a3 = 0.f, ss = 0.f;
    const size_t rbase = (size_t)r * NN;

    for (int base = 0; base < deg; base += 32) {
        int nv = min(32, deg - base);
        int sl = g_srcs[off + base + (lane < nv ? lane : 0)];
        for (int j = 0; j < nv; j += 4) {
            int s0 = __shfl_sync(0xffffffffu, sl, j);
            int s1 = __shfl_sync(0xffffffffu, sl, (j + 1) & 31);
            int s2 = __shfl_sync(0xffffffffu, sl, (j + 2) & 31);
            int s3 = __shfl_sync(0xffffffffu, sl, (j + 3) & 31);
            bool v1 = j + 1 < nv, v2 = j + 2 < nv, v3 = j + 3 < nv;
            if (!v1) s1 = s0;
            if (!v2) s2 = s0;
            if (!v3) s3 = s0;
            float el0 = __ldg(&g_el[(rbase + s0) * HH + h]);
            float el1 = v1 ? __ldg(&g_el[(rbase + s1) * HH + h]) : -1e30f;
            float el2 = v2 ? __ldg(&g_el[(rbase + s2) * HH + h]) : -1e30f;
            float el3 = v3 ? __ldg(&g_el[(rbase + s3) * HH + h]) : -1e30f;
            float4 hv0 = *(const float4*)(g_hs + (rbase + s0) * HD + lane * 4);
            float4 hv1 = *(const float4*)(g_hs + (rbase + s1) * HD + lane * 4);
            float4 hv2 = *(const float4*)(g_hs + (rbase + s2) * HD + lane * 4);
            float4 hv3 = *(const float4*)(g_hs + (rbase + s3) * HD + lane * 4);
            float e0 = el0 + er; e0 = e0 > 0.f ? e0 : 0.2f * e0;
            float e1 = el1 + er; e1 = e1 > 0.f ? e1 : 0.2f * e1;
            float e2 = el2 + er; e2 = e2 > 0.f ? e2 : 0.2f * e2;
            float e3 = el3 + er; e3 = e3 > 0.f ? e3 : 0.2f * e3;
            float x0 = expf(e0), x1 = expf(e1), x2 = expf(e2), x3 = expf(e3);
            a0 += x0 * hv0.x + x1 * hv1.x + x2 * hv2.x + x3 * hv3.x;
            a1 += x0 * hv0.y + x1 * hv1.y + x2 * hv2.y + x3 * hv3.y;
            a2 += x0 * hv0.z + x1 * hv1.z + x2 * hv2.z + x3 * hv3.z;
            a3 += x0 * hv0.w + x1 * hv1.w + x2 * hv2.w + x3 * hv3.w;
            ss += x0 + x1 + x2 + x3;
        }
    }

    float si = 1.f / (ss + 1e-9f);
    float4 bg = *(const float4*)(bias_g + r * HD + lane * 4);
    float z0 = a0 * si + bg.x, z1 = a1 * si + bg.y;
    float z2 = a2 * si + bg.z, z3 = a3 * si + bg.w;
    z0 = z0 > 0.f ? z0 : expm1f(z0);
    z1 = z1 > 0.f ? z1 : expm1f(z1);
    z2 = z2 > 0.f ? z2 : expm1f(z2);
    z3 = z3 > 0.f ? z3 : expm1f(z3);
    *(float4*)(g_z + (size_t)w * HD + lane * 4) = make_float4(z0, z1, z2, z3);
}

// ---------------- semantic GEMM ----------------
__global__ __launch_bounds__(256) void k_semantic_mma(const float* __restrict__ b1,
                                                      const float* __restrict__ W2) {
    extern __shared__ float sm[];
    float* Ws = sm;
    float* As = sm + 128 * WS_STR;
    __shared__ float sacc;
    int tid = threadIdx.x;
    if (tid == 0) sacc = 0.f;
    int r = blockIdx.y;
    int row0 = blockIdx.x * 128;
    const float* A = g_z + (size_t)r * NN * HD;

    const float4* Wt4 = (const float4*)g_W1T;
    #pragma unroll
    for (int i = 0; i < 16; i++) {
        int idx = tid + i * 256;
        int n = idx >> 5, kq = idx & 31;
        *(float4*)(Ws + n * WS_STR + kq * 4) = Wt4[idx];
    }

    int grow = row0 + (tid >> 1);
    int koffA = (tid & 1) * 8;
    float4 areg0, areg1;
    float4 z4 = make_float4(0.f, 0.f, 0.f, 0.f);

    uint32_t sbase = (uint32_t)__cvta_generic_to_shared(sm);
    uint32_t asbase = sbase + 128 * WS_STR * 4;

    int lane = tid & 31, warp = tid >> 5;
    int warp_m = warp >> 1, warp_n = warp & 1;
    int n0 = warp_n * 64;
    int g = lane >> 2, tg = lane & 3;
    int grp = lane >> 3, rin = lane & 7;
    int arow = (grp & 1) * 8 + rin;
    int akoff = (grp >> 1) * 4;
    int brow = (grp >> 1) * 8 + rin;
    int bkoff = (grp & 1) * 4;

    uint32_t aAddr[2], bAddr[4];
    #pragma unroll
    for (int mt = 0; mt < 2; mt++)
        aAddr[mt] = asbase + ((warp_m * 32 + mt * 16 + arow) * AS_STR + akoff) * 4;
    #pragma unroll
    for (int pi = 0; pi < 4; pi++)
        bAddr[pi] = sbase + ((n0 + pi * 16 + brow) * WS_STR + bkoff) * 4;

    float c[2][8][4];
    #pragma unroll
    for (int mt = 0; mt < 2; mt++)
        #pragma unroll
        for (int nt = 0; nt < 8; nt++)
            #pragma unroll
            for (int q = 0; q < 4; q++) c[mt][nt][q] = 0.f;

    if (grow < NN) {
        const float4* p = (const float4*)(A + (size_t)grow * HD + koffA);
        areg0 = p[0]; areg1 = p[1];
    } else { areg0 = z4; areg1 = z4; }

    for (int kb = 0; kb < 8; kb++) {
        {
            float* dst = As + (kb & 1) * AS_BUF + (tid >> 1) * AS_STR + koffA;
            dst[0] = to_tf32(areg0.x); dst[1] = to_tf32(areg0.y);
            dst[2] = to_tf32(areg0.z); dst[3] = to_tf32(areg0.w);
            dst[4] = to_tf32(areg1.x); dst[5] = to_tf32(areg1.y);
            dst[6] = to_tf32(areg1.z); dst[7] = to_tf32(areg1.w);
        }
        if (kb < 7) {
            if (grow < NN) {
                const float4* p = (const float4*)(A + (size_t)grow * HD + (kb + 1) * 16 + koffA);
                areg0 = p[0]; areg1 = p[1];
            } else { areg0 = z4; areg1 = z4; }
        }
        __syncthreads();
        uint32_t abufoff = (kb & 1) * AS_BUF * 4;
        #pragma unroll
        for (int k8 = 0; k8 < 2; k8++) {
            uint32_t a[2][4], b[8][2];
            #pragma unroll
            for (int mt = 0; mt < 2; mt++)
                LDSM4(a[mt][0], a[mt][1], a[mt][2], a[mt][3],
                      aAddr[mt] + abufoff + k8 * 32);
            #pragma unroll
            for (int pi = 0; pi < 4; pi++)
                LDSM4(b[2 * pi][0], b[2 * pi][1], b[2 * pi + 1][0], b[2 * pi + 1][1],
                      bAddr[pi] + (kb * 16 + k8 * 8) * 4);
            #pragma unroll
            for (int mt = 0; mt < 2; mt++)
                #pragma unroll
                for (int nt = 0; nt < 8; nt++)
                    MMA_TF32(c[mt][nt], a[mt], b[nt]);
        }
    }

    float2 b12[8], w22[8];
    #pragma unroll
    for (int nt = 0; nt < 8; nt++) {
        b12[nt] = *(const float2*)(b1 + n0 + nt * 8 + 2 * tg);
        w22[nt] = *(const float2*)(W2 + n0 + nt * 8 + 2 * tg);
    }
    float ps[2][2] = {{0.f, 0.f}, {0.f, 0.f}};
    #pragma unroll
    for (int mt = 0; mt < 2; mt++)
        #pragma unroll
        for (int nt = 0; nt < 8; nt++) {
            ps[mt][0] += tanhf(c[mt][nt][0] + b12[nt].x) * w22[nt].x
                       + tanhf(c[mt][nt][1] + b12[nt].y) * w22[nt].y;
            ps[mt][1] += tanhf(c[mt][nt][2] + b12[nt].x) * w22[nt].x
                       + tanhf(c[mt][nt][3] + b12[nt].y) * w22[nt].y;
        }
    #pragma unroll
    for (int off = 1; off < 4; off <<= 1)
        #pragma unroll
        for (int mt = 0; mt < 2; mt++) {
            ps[mt][0] += __shfl_xor_sync(0xffffffffu, ps[mt][0], off);
            ps[mt][1] += __shfl_xor_sync(0xffffffffu, ps[mt][1], off);
        }
    if (tg == 0) {
        float loc = 0.f;
        #pragma unroll
        for (int mt = 0; mt < 2; mt++)
            #pragma unroll
            for (int rh = 0; rh < 2; rh++) {
                int row = row0 + warp_m * 32 + mt * 16 + g + rh * 8;
                if (row < NN) loc += ps[mt][rh];
            }
        atomicAdd(&sacc, loc);
    }
    __syncthreads();
    if (tid == 0) atomicAdd(&g_wsum[r], sacc);
}

// ---------------- semantic softmax ----------------
__global__ void k_softmax(float* __restrict__ out) {
    int t = threadIdx.x;
    if (t < RR) {
        float w0 = g_wsum[0] / (float)NN;
        float w1 = g_wsum[1] / (float)NN;
        float w2 = g_wsum[2] / (float)NN;
        float mx = fmaxf(w0, fmaxf(w1, w2));
        float e0 = expf(w0 - mx), e1 = expf(w1 - mx), e2 = expf(w2 - mx);
        float s = e0 + e1 + e2;
        float a = (t == 0 ? e0 : (t == 1 ? e1 : e2)) / s;
        g_a[t] = a;
        out[(size_t)NN * HD + t] = a;
    }
}

// ---------------- final combine ----------------
__global__ void k_final(float* __restrict__ out) {
    int idx = blockIdx.x * blockDim.x + threadIdx.x;
    const int TOT4 = NN * HD / 4;
    if (idx >= TOT4) return;
    float a0 = __ldg(&g_a[0]), a1 = __ldg(&g_a[1]), a2 = __ldg(&g_a[2]);
    const float4* z = (const float4*)g_z;
    float4 z0 = z[idx], z1 = z[idx + TOT4], z2 = z[idx + 2 * TOT4];
    float4 o;
    o.x = a0 * z0.x + a1 * z1.x + a2 * z2.x;
    o.y = a0 * z0.y + a1 * z1.y + a2 * z2.y;
    o.z = a0 * z0.z + a1 * z1.z + a2 * z2.z;
    o.w = a0 * z0.w + a1 * z1.w + a2 * z2.w;
    ((float4*)out)[idx] = o;
}

// ---------------- launch ----------------
extern "C" void kernel_launch(void* const* d_in, const int* in_sizes, int n_in,
                              void* d_out, int out_size) {
    const float* dst_feat  = (const float*)d_in[0];
    const float* src_feats = (const float*)d_in[1];
    const int*   src_idx   = (const int*)d_in[2];
    const int*   dst_idx   = (const int*)d_in[3];
    const float* Wt_dst    = (const float*)d_in[4];
    const float* bt_dst    = (const float*)d_in[5];
    const float* Wt_src    = (const float*)d_in[6];
    const float* bt_src    = (const float*)d_in[7];
    const float* Wg        = (const float*)d_in[8];
    const float* attn_l    = (const float*)d_in[9];
    const float* attn_r    = (const float*)d_in[10];
    const float* bias_g    = (const float*)d_in[11];
    const float* W1        = (const float*)d_in[12];
    const float* b1        = (const float*)d_in[13];
    const float* W2        = (const float*)d_in[14];
    float* out = (float*)d_out;

    size_t smem_mma = (size_t)SMEM_FLOATS * sizeof(float);
    cudaFuncSetAttribute(k_gemm_hs_mma, cudaFuncAttributeMaxDynamicSharedMemorySize, (int)smem_mma);
    cudaFuncSetAttribute(k_semantic_mma, cudaFuncAttributeMaxDynamicSharedMemorySize, (int)smem_mma);

    int eth = RR * EE;
    k_prep<<<PB_TOTAL, 128>>>(Wt_src, bt_src, Wg, W1, attn_r, Wt_dst, bt_dst);

    // CSR build
    k_hist<<<(eth + 255) / 256, 256>>>(dst_idx);
    k_scan1<<<(NTOT + 1023) / 1024, 256>>>();
    k_scan2<<<1, 512>>>();
    k_scan3<<<(NTOT + 255) / 256, 256>>>();
    k_fill<<<(eth + 255) / 256, 256>>>(src_idx, dst_idx);

    dim3 ggrid((NN + 127) / 128, RR);
    k_gemm_hs_mma<<<ggrid, 256, smem_mma>>>(src_feats, attn_l);
    k_er<<<(NN + 7) / 8, 256>>>(dst_feat);

    k_gather<<<(NTOT * 32 + 255) / 256, 256>>>(bias_g);

    k_semantic_mma<<<ggrid, 256, smem_mma>>>(b1, W2);
    k_softmax<<<1, 32>>>(out);
    k_final<<<(NN * HD / 4 + 255) / 256, 256>>>(out);
}

// round 9
// speedup vs baseline: 1.1122x; 1.1122x over previous
#include <cuda_runtime.h>
#include <math.h>
#include <stdint.h>

#define NN 100000
#define RR 3
#define EE 320000
#define HIDD 128
#define HH 4
#define HD 128
#define NTOT (RR * NN)

// ---------------- device scratch ----------------
__device__ float g_hs  [(size_t)RR * NN * HD];
__device__ float g_z   [(size_t)RR * NN * HD];
__device__ float g_el  [(size_t)RR * NN * HH];
__device__ float g_er  [(size_t)RR * NN * HH];
__device__ float g_WcT [RR * HIDD * HD];
__device__ float g_bc  [RR * HD];
__device__ float g_W1T [HD * 128];
__device__ float g_u   [RR * HIDD * HH];
__device__ float g_V   [RR * HIDD * HH];
__device__ float g_c   [RR * HH];
__device__ float g_wsum[RR];
__device__ float g_a   [RR];
// CSR scratch
__device__ int g_deg [NTOT];
__device__ int g_off [NTOT];   // local (within-1024-block) exclusive prefix
__device__ int g_cur [NTOT];   // running cursor (local base)
__device__ int g_bsum[512];    // per-1024-block exclusive sums
__device__ int g_srcs[RR * EE];

// ---------------- helpers ----------------
__device__ __forceinline__ float to_tf32(float x) {
    uint32_t o;
    asm("cvt.rna.tf32.f32 %0, %1;" : "=r"(o) : "f"(x));
    return __uint_as_float(o);
}

#define LDSM4(r0, r1, r2, r3, addr) \
    asm volatile("ldmatrix.sync.aligned.m8n8.x4.shared.b16 {%0,%1,%2,%3}, [%4];" \
                 : "=r"(r0), "=r"(r1), "=r"(r2), "=r"(r3) : "r"(addr))

#define MMA_TF32(c, a, b) \
    asm volatile("mma.sync.aligned.m16n8k8.row.col.f32.tf32.tf32.f32 " \
                 "{%0,%1,%2,%3},{%4,%5,%6,%7},{%8,%9},{%0,%1,%2,%3};" \
                 : "+f"((c)[0]), "+f"((c)[1]), "+f"((c)[2]), "+f"((c)[3]) \
                 : "r"((a)[0]), "r"((a)[1]), "r"((a)[2]), "r"((a)[3]), \
                   "r"((b)[0]), "r"((b)[1]))

// ---------------- zero ----------------
__global__ void k_zero() {
    int i = blockIdx.x * blockDim.x + threadIdx.x;
    if (i < NTOT) g_deg[i] = 0;
    if (i < RR) g_wsum[i] = 0.f;
}

// ---------------- CSR build ----------------
__global__ void k_hist(const int* __restrict__ dst_idx) {
    int idx = blockIdx.x * blockDim.x + threadIdx.x;
    if (idx >= RR * EE) return;
    int r = idx / EE;
    atomicAdd(&g_deg[r * NN + dst_idx[idx]], 1);
}

__global__ void k_scan1() {
    __shared__ int ssum[256];
    int t = threadIdx.x;
    int base = blockIdx.x * 1024 + t * 4;
    int v0 = base + 0 < NTOT ? g_deg[base + 0] : 0;
    int v1 = base + 1 < NTOT ? g_deg[base + 1] : 0;
    int v2 = base + 2 < NTOT ? g_deg[base + 2] : 0;
    int v3 = base + 3 < NTOT ? g_deg[base + 3] : 0;
    int tot = v0 + v1 + v2 + v3;
    ssum[t] = tot;
    __syncthreads();
    for (int o = 1; o < 256; o <<= 1) {
        int x = t >= o ? ssum[t - o] : 0;
        __syncthreads();
        ssum[t] += x;
        __syncthreads();
    }
    int ex = ssum[t] - tot;
    if (t == 255) g_bsum[blockIdx.x] = ssum[255];
    // write local exclusive prefix to BOTH off and cur (consumers add g_bsum)
    if (base + 0 < NTOT) { g_off[base + 0] = ex;               g_cur[base + 0] = ex; }
    if (base + 1 < NTOT) { g_off[base + 1] = ex + v0;          g_cur[base + 1] = ex + v0; }
    if (base + 2 < NTOT) { g_off[base + 2] = ex + v0 + v1;     g_cur[base + 2] = ex + v0 + v1; }
    if (base + 3 < NTOT) { g_off[base + 3] = ex + v0 + v1 + v2; g_cur[base + 3] = ex + v0 + v1 + v2; }
}

__global__ void k_scan2() {
    __shared__ int s[512];
    int t = threadIdx.x;
    const int NB = (NTOT + 1023) / 1024;
    int v = t < NB ? g_bsum[t] : 0;
    s[t] = v;
    __syncthreads();
    for (int o = 1; o < 512; o <<= 1) {
        int x = t >= o ? s[t - o] : 0;
        __syncthreads();
        s[t] += x;
        __syncthreads();
    }
    if (t < NB) g_bsum[t] = s[t] - v;
}

__global__ void k_fill(const int* __restrict__ src_idx, const int* __restrict__ dst_idx) {
    int idx = blockIdx.x * blockDim.x + threadIdx.x;
    if (idx >= RR * EE) return;
    int r = idx / EE;
    int node = r * NN + dst_idx[idx];
    int pos = atomicAdd(&g_cur[node], 1) + g_bsum[node >> 10];
    g_srcs[pos] = src_idx[idx];
}

// ---------------- weight composition ----------------
__global__ void k_combine(const float* __restrict__ Wt_src,
                          const float* __restrict__ bt_src,
                          const float* __restrict__ Wg) {
    int b = blockIdx.x;
    int r = b / (HIDD + 1);
    int i = b % (HIDD + 1);
    int tid = threadIdx.x;
    __shared__ float srow[HIDD];
    const float* Wgr = Wg + (size_t)r * HIDD * HD;
    srow[tid] = (i < HIDD) ? Wt_src[((size_t)r * HIDD + i) * HIDD + tid]
                           : bt_src[r * HIDD + tid];
    __syncthreads();
    float acc = 0.f;
    #pragma unroll 8
    for (int k = 0; k < HIDD; k++) acc += srow[k] * Wgr[k * HD + tid];
    if (i < HIDD) g_WcT[((size_t)r * HIDD + tid) * HIDD + i] = to_tf32(acc);
    else          g_bc[r * HD + tid] = acc;
}

__global__ void k_w1t(const float* __restrict__ W1) {
    int idx = blockIdx.x * blockDim.x + threadIdx.x;
    if (idx >= HD * 128) return;
    int n = idx / 128, k = idx % 128;
    g_W1T[n * 128 + k] = to_tf32(W1[k * 128 + n]);
}

__global__ void k_u(const float* __restrict__ Wg, const float* __restrict__ attn_r) {
    int idx = blockIdx.x * blockDim.x + threadIdx.x;
    if (idx >= RR * HIDD * HH) return;
    int r = idx / (HIDD * HH);
    int rem = idx % (HIDD * HH);
    int k = rem / HH, h = rem % HH;
    const float* wg = Wg + (size_t)r * HIDD * HD + k * HD + h * 32;
    const float* ar = attn_r + r * HD + h * 32;
    float s = 0.f;
    #pragma unroll
    for (int d = 0; d < 32; d++) s += wg[d] * ar[d];
    g_u[idx] = s;
}

__global__ void k_V(const float* __restrict__ Wt_dst, const float* __restrict__ bt_dst) {
    int idx = blockIdx.x * blockDim.x + threadIdx.x;
    if (idx >= RR * HIDD * HH) return;
    int r = idx / (HIDD * HH);
    int rem = idx % (HIDD * HH);
    int f = rem / HH, h = rem % HH;
    const float* u = g_u + r * HIDD * HH;
    float s = 0.f;
    for (int k = 0; k < HIDD; k++) s += Wt_dst[f * HIDD + k] * u[k * HH + h];
    g_V[idx] = s;
    if (f == 0) {
        float c = 0.f;
        for (int k = 0; k < HIDD; k++) c += bt_dst[k] * u[k * HH + h];
        g_c[r * HH + h] = c;
    }
}

// ---------------- TF32 MMA GEMM geometry ----------------
constexpr int AS_STR = 20;
constexpr int WS_STR = 132;
constexpr int AS_BUF = 128 * AS_STR;
constexpr int SMEM_FLOATS = 128 * WS_STR + 2 * AS_BUF;

// ---------------- hs GEMM: g_hs = A @ Wc + bc, el epilogue ----------------
__global__ __launch_bounds__(256) void k_gemm_hs_mma(const float* __restrict__ src_feats,
                                                     const float* __restrict__ attn_l) {
    extern __shared__ float sm[];
    float* Ws = sm;
    float* As = sm + 128 * WS_STR;
    int tid = threadIdx.x;
    int r = blockIdx.y;
    int row0 = blockIdx.x * 128;
    const float* A = src_feats + (size_t)r * NN * HIDD;

    const float4* Wt4 = (const float4*)(g_WcT + (size_t)r * HIDD * HD);
    #pragma unroll
    for (int i = 0; i < 16; i++) {
        int idx = tid + i * 256;
        int n = idx >> 5, kq = idx & 31;
        *(float4*)(Ws + n * WS_STR + kq * 4) = Wt4[idx];
    }

    int grow = row0 + (tid >> 1);
    int koffA = (tid & 1) * 8;
    float4 areg0, areg1;
    float4 z4 = make_float4(0.f, 0.f, 0.f, 0.f);

    uint32_t sbase = (uint32_t)__cvta_generic_to_shared(sm);
    uint32_t asbase = sbase + 128 * WS_STR * 4;

    int lane = tid & 31, warp = tid >> 5;
    int warp_m = warp >> 1, warp_n = warp & 1;
    int n0 = warp_n * 64;
    int g = lane >> 2, tg = lane & 3;
    int grp = lane >> 3, rin = lane & 7;
    int arow = (grp & 1) * 8 + rin;
    int akoff = (grp >> 1) * 4;
    int brow = (grp >> 1) * 8 + rin;
    int bkoff = (grp & 1) * 4;

    uint32_t aAddr[2], bAddr[4];
    #pragma unroll
    for (int mt = 0; mt < 2; mt++)
        aAddr[mt] = asbase + ((warp_m * 32 + mt * 16 + arow) * AS_STR + akoff) * 4;
    #pragma unroll
    for (int pi = 0; pi < 4; pi++)
        bAddr[pi] = sbase + ((n0 + pi * 16 + brow) * WS_STR + bkoff) * 4;

    float c[2][8][4];
    #pragma unroll
    for (int mt = 0; mt < 2; mt++)
        #pragma unroll
        for (int nt = 0; nt < 8; nt++)
            #pragma unroll
            for (int q = 0; q < 4; q++) c[mt][nt][q] = 0.f;

    if (grow < NN) {
        const float4* p = (const float4*)(A + (size_t)grow * HIDD + koffA);
        areg0 = p[0]; areg1 = p[1];
    } else { areg0 = z4; areg1 = z4; }

    for (int kb = 0; kb < 8; kb++) {
        {
            float* dst = As + (kb & 1) * AS_BUF + (tid >> 1) * AS_STR + koffA;
            dst[0] = to_tf32(areg0.x); dst[1] = to_tf32(areg0.y);
            dst[2] = to_tf32(areg0.z); dst[3] = to_tf32(areg0.w);
            dst[4] = to_tf32(areg1.x); dst[5] = to_tf32(areg1.y);
            dst[6] = to_tf32(areg1.z); dst[7] = to_tf32(areg1.w);
        }
        if (kb < 7) {
            if (grow < NN) {
                const float4* p = (const float4*)(A + (size_t)grow * HIDD + (kb + 1) * 16 + koffA);
                areg0 = p[0]; areg1 = p[1];
            } else { areg0 = z4; areg1 = z4; }
        }
        __syncthreads();
        uint32_t abufoff = (kb & 1) * AS_BUF * 4;
        #pragma unroll
        for (int k8 = 0; k8 < 2; k8++) {
            uint32_t a[2][4], b[8][2];
            #pragma unroll
            for (int mt = 0; mt < 2; mt++)
                LDSM4(a[mt][0], a[mt][1], a[mt][2], a[mt][3],
                      aAddr[mt] + abufoff + k8 * 32);
            #pragma unroll
            for (int pi = 0; pi < 4; pi++)
                LDSM4(b[2 * pi][0], b[2 * pi][1], b[2 * pi + 1][0], b[2 * pi + 1][1],
                      bAddr[pi] + (kb * 16 + k8 * 8) * 4);
            #pragma unroll
            for (int mt = 0; mt < 2; mt++)
                #pragma unroll
                for (int nt = 0; nt < 8; nt++)
                    MMA_TF32(c[mt][nt], a[mt], b[nt]);
        }
    }

    float2 bc2[8], al2[8];
    #pragma unroll
    for (int nt = 0; nt < 8; nt++) {
        bc2[nt] = *(const float2*)(g_bc + r * HD + n0 + nt * 8 + 2 * tg);
        al2[nt] = *(const float2*)(attn_l + r * HD + n0 + nt * 8 + 2 * tg);
    }
    float elp[2][2][2];
    #pragma unroll
    for (int mt = 0; mt < 2; mt++)
        #pragma unroll
        for (int rh = 0; rh < 2; rh++) { elp[mt][rh][0] = 0.f; elp[mt][rh][1] = 0.f; }

    #pragma unroll
    for (int mt = 0; mt < 2; mt++) {
        int rowa = row0 + warp_m * 32 + mt * 16 + g;
        #pragma unroll
        for (int nt = 0; nt < 8; nt++) {
            float c0 = c[mt][nt][0] + bc2[nt].x, c1 = c[mt][nt][1] + bc2[nt].y;
            float c2 = c[mt][nt][2] + bc2[nt].x, c3 = c[mt][nt][3] + bc2[nt].y;
            int h = nt >> 2;
            elp[mt][0][h] += c0 * al2[nt].x + c1 * al2[nt].y;
            elp[mt][1][h] += c2 * al2[nt].x + c3 * al2[nt].y;
            if (rowa < NN)
                *(float2*)(g_hs + ((size_t)r * NN + rowa) * HD + n0 + nt * 8 + 2 * tg) = make_float2(c0, c1);
            if (rowa + 8 < NN)
                *(float2*)(g_hs + ((size_t)r * NN + rowa + 8) * HD + n0 + nt * 8 + 2 * tg) = make_float2(c2, c3);
        }
    }
    #pragma unroll
    for (int off = 1; off < 4; off <<= 1)
        #pragma unroll
        for (int mt = 0; mt < 2; mt++)
            #pragma unroll
            for (int rh = 0; rh < 2; rh++) {
                elp[mt][rh][0] += __shfl_xor_sync(0xffffffffu, elp[mt][rh][0], off);
                elp[mt][rh][1] += __shfl_xor_sync(0xffffffffu, elp[mt][rh][1], off);
            }
    if (tg == 0) {
        #pragma unroll
        for (int mt = 0; mt < 2; mt++)
            #pragma unroll
            for (int rh = 0; rh < 2; rh++) {
                int row = row0 + warp_m * 32 + mt * 16 + g + rh * 8;
                if (row < NN) {
                    g_el[((size_t)r * NN + row) * HH + warp_n * 2 + 0] = elp[mt][rh][0];
                    g_el[((size_t)r * NN + row) * HH + warp_n * 2 + 1] = elp[mt][rh][1];
                }
            }
    }
}

// ---------------- er: dst_feat @ V ----------------
__global__ void k_er(const float* __restrict__ dst_feat) {
    __shared__ float sV[RR * HIDD * HH];
    __shared__ float sc[RR * HH];
    int tid = threadIdx.x;
    for (int i = tid; i < RR * HIDD * HH; i += blockDim.x) sV[i] = g_V[i];
    if (tid < RR * HH) sc[tid] = g_c[tid];
    __syncthreads();
    int node = blockIdx.x * 8 + (tid >> 5);
    int lane = tid & 31;
    if (node >= NN) return;
    float4 f = ((const float4*)dst_feat)[(size_t)node * 32 + lane];
    #pragma unroll
    for (int r = 0; r < RR; r++) {
        const float* base = sV + r * HIDD * HH;
        float4 v0 = *(const float4*)(base + (lane * 4 + 0) * 4);
        float4 v1 = *(const float4*)(base + (lane * 4 + 1) * 4);
        float4 v2 = *(const float4*)(base + (lane * 4 + 2) * 4);
        float4 v3 = *(const float4*)(base + (lane * 4 + 3) * 4);
        float p0 = f.x * v0.x + f.y * v1.x + f.z * v2.x + f.w * v3.x;
        float p1 = f.x * v0.y + f.y * v1.y + f.z * v2.y + f.w * v3.y;
        float p2 = f.x * v0.z + f.y * v1.z + f.z * v2.z + f.w * v3.z;
        float p3 = f.x * v0.w + f.y * v1.w + f.z * v2.w + f.w * v3.w;
        #pragma unroll
        for (int off = 16; off; off >>= 1) {
            p0 += __shfl_xor_sync(0xffffffffu, p0, off);
            p1 += __shfl_xor_sync(0xffffffffu, p1, off);
            p2 += __shfl_xor_sync(0xffffffffu, p2, off);
            p3 += __shfl_xor_sync(0xffffffffu, p3, off);
        }
        if (lane == 0) {
            float* erp = g_er + ((size_t)r * NN + node) * HH;
            erp[0] = p0 + sc[r * HH + 0];
            erp[1] = p1 + sc[r * HH + 1];
            erp[2] = p2 + sc[r * HH + 2];
            erp[3] = p3 + sc[r * HH + 3];
        }
    }
}

// ---------------- pull-based aggregation: warp per (r,dst), index prefetch ----------------
__global__ __launch_bounds__(256) void k_gather(const float* __restrict__ bias_g) {
    int w = (blockIdx.x * 256 + threadIdx.x) >> 5;
    int lane = threadIdx.x & 31;
    if (w >= NTOT) return;
    int r = w / NN;
    int off = g_off[w] + g_bsum[w >> 10];
    int deg = g_deg[w];
    int h = lane >> 3;
    float er = g_er[(size_t)w * HH + h];
    float a0 = 0.f, a1 = 0.f, a2 = 0.f, a3 = 0.f, ss = 0.f;
    const size_t rbase = (size_t)r * NN;

    int s = deg > 0 ? g_srcs[off] : 0;
    for (int j = 0; j < deg; j++) {
        int snext = (j + 1 < deg) ? g_srcs[off + j + 1] : 0;   // prefetch
        float el = __ldg(&g_el[(rbase + s) * HH + h]);
        float4 hv = *(const float4*)(g_hs + (rbase + s) * HD + lane * 4);
        float e = el + er;
        e = e > 0.f ? e : 0.2f * e;
        float ex = expf(e);
        a0 += ex * hv.x; a1 += ex * hv.y; a2 += ex * hv.z; a3 += ex * hv.w;
        ss += ex;
        s = snext;
    }
    float si = 1.f / (ss + 1e-9f);
    float4 bg = *(const float4*)(bias_g + r * HD + lane * 4);
    float z0 = a0 * si + bg.x, z1 = a1 * si + bg.y;
    float z2 = a2 * si + bg.z, z3 = a3 * si + bg.w;
    z0 = z0 > 0.f ? z0 : expm1f(z0);
    z1 = z1 > 0.f ? z1 : expm1f(z1);
    z2 = z2 > 0.f ? z2 : expm1f(z2);
    z3 = z3 > 0.f ? z3 : expm1f(z3);
    *(float4*)(g_z + (size_t)w * HD + lane * 4) = make_float4(z0, z1, z2, z3);
}

// ---------------- semantic GEMM: reads elu'd z directly ----------------
__global__ __launch_bounds__(256) void k_semantic_mma(const float* __restrict__ b1,
                                                      const float* __restrict__ W2) {
    extern __shared__ float sm[];
    float* Ws = sm;
    float* As = sm + 128 * WS_STR;
    __shared__ float sacc;
    int tid = threadIdx.x;
    if (tid == 0) sacc = 0.f;
    int r = blockIdx.y;
    int row0 = blockIdx.x * 128;
    const float* A = g_z + (size_t)r * NN * HD;

    const float4* Wt4 = (const float4*)g_W1T;
    #pragma unroll
    for (int i = 0; i < 16; i++) {
        int idx = tid + i * 256;
        int n = idx >> 5, kq = idx & 31;
        *(float4*)(Ws + n * WS_STR + kq * 4) = Wt4[idx];
    }

    int grow = row0 + (tid >> 1);
    int koffA = (tid & 1) * 8;
    float4 areg0, areg1;
    float4 z4 = make_float4(0.f, 0.f, 0.f, 0.f);

    uint32_t sbase = (uint32_t)__cvta_generic_to_shared(sm);
    uint32_t asbase = sbase + 128 * WS_STR * 4;

    int lane = tid & 31, warp = tid >> 5;
    int warp_m = warp >> 1, warp_n = warp & 1;
    int n0 = warp_n * 64;
    int g = lane >> 2, tg = lane & 3;
    int grp = lane >> 3, rin = lane & 7;
    int arow = (grp & 1) * 8 + rin;
    int akoff = (grp >> 1) * 4;
    int brow = (grp >> 1) * 8 + rin;
    int bkoff = (grp & 1) * 4;

    uint32_t aAddr[2], bAddr[4];
    #pragma unroll
    for (int mt = 0; mt < 2; mt++)
        aAddr[mt] = asbase + ((warp_m * 32 + mt * 16 + arow) * AS_STR + akoff) * 4;
    #pragma unroll
    for (int pi = 0; pi < 4; pi++)
        bAddr[pi] = sbase + ((n0 + pi * 16 + brow) * WS_STR + bkoff) * 4;

    float c[2][8][4];
    #pragma unroll
    for (int mt = 0; mt < 2; mt++)
        #pragma unroll
        for (int nt = 0; nt < 8; nt++)
            #pragma unroll
            for (int q = 0; q < 4; q++) c[mt][nt][q] = 0.f;

    if (grow < NN) {
        const float4* p = (const float4*)(A + (size_t)grow * HD + koffA);
        areg0 = p[0]; areg1 = p[1];
    } else { areg0 = z4; areg1 = z4; }

    for (int kb = 0; kb < 8; kb++) {
        {
            float* dst = As + (kb & 1) * AS_BUF + (tid >> 1) * AS_STR + koffA;
            dst[0] = to_tf32(areg0.x); dst[1] = to_tf32(areg0.y);
            dst[2] = to_tf32(areg0.z); dst[3] = to_tf32(areg0.w);
            dst[4] = to_tf32(areg1.x); dst[5] = to_tf32(areg1.y);
            dst[6] = to_tf32(areg1.z); dst[7] = to_tf32(areg1.w);
        }
        if (kb < 7) {
            if (grow < NN) {
                const float4* p = (const float4*)(A + (size_t)grow * HD + (kb + 1) * 16 + koffA);
                areg0 = p[0]; areg1 = p[1];
            } else { areg0 = z4; areg1 = z4; }
        }
        __syncthreads();
        uint32_t abufoff = (kb & 1) * AS_BUF * 4;
        #pragma unroll
        for (int k8 = 0; k8 < 2; k8++) {
            uint32_t a[2][4], b[8][2];
            #pragma unroll
            for (int mt = 0; mt < 2; mt++)
                LDSM4(a[mt][0], a[mt][1], a[mt][2], a[mt][3],
                      aAddr[mt] + abufoff + k8 * 32);
            #pragma unroll
            for (int pi = 0; pi < 4; pi++)
                LDSM4(b[2 * pi][0], b[2 * pi][1], b[2 * pi + 1][0], b[2 * pi + 1][1],
                      bAddr[pi] + (kb * 16 + k8 * 8) * 4);
            #pragma unroll
            for (int mt = 0; mt < 2; mt++)
                #pragma unroll
                for (int nt = 0; nt < 8; nt++)
                    MMA_TF32(c[mt][nt], a[mt], b[nt]);
        }
    }

    float2 b12[8], w22[8];
    #pragma unroll
    for (int nt = 0; nt < 8; nt++) {
        b12[nt] = *(const float2*)(b1 + n0 + nt * 8 + 2 * tg);
        w22[nt] = *(const float2*)(W2 + n0 + nt * 8 + 2 * tg);
    }
    float ps[2][2] = {{0.f, 0.f}, {0.f, 0.f}};
    #pragma unroll
    for (int mt = 0; mt < 2; mt++)
        #pragma unroll
        for (int nt = 0; nt < 8; nt++) {
            ps[mt][0] += tanhf(c[mt][nt][0] + b12[nt].x) * w22[nt].x
                       + tanhf(c[mt][nt][1] + b12[nt].y) * w22[nt].y;
            ps[mt][1] += tanhf(c[mt][nt][2] + b12[nt].x) * w22[nt].x
                       + tanhf(c[mt][nt][3] + b12[nt].y) * w22[nt].y;
        }
    #pragma unroll
    for (int off = 1; off < 4; off <<= 1)
        #pragma unroll
        for (int mt = 0; mt < 2; mt++) {
            ps[mt][0] += __shfl_xor_sync(0xffffffffu, ps[mt][0], off);
            ps[mt][1] += __shfl_xor_sync(0xffffffffu, ps[mt][1], off);
        }
    if (tg == 0) {
        float loc = 0.f;
        #pragma unroll
        for (int mt = 0; mt < 2; mt++)
            #pragma unroll
            for (int rh = 0; rh < 2; rh++) {
                int row = row0 + warp_m * 32 + mt * 16 + g + rh * 8;
                if (row < NN) loc += ps[mt][rh];
            }
        atomicAdd(&sacc, loc);
    }
    __syncthreads();
    if (tid == 0) atomicAdd(&g_wsum[r], sacc);
}

// ---------------- semantic softmax ----------------
__global__ void k_softmax(float* __restrict__ out) {
    int t = threadIdx.x;
    if (t < RR) {
        float w0 = g_wsum[0] / (float)NN;
        float w1 = g_wsum[1] / (float)NN;
        float w2 = g_wsum[2] / (float)NN;
        float mx = fmaxf(w0, fmaxf(w1, w2));
        float e0 = expf(w0 - mx), e1 = expf(w1 - mx), e2 = expf(w2 - mx);
        float s = e0 + e1 + e2;
        float a = (t == 0 ? e0 : (t == 1 ? e1 : e2)) / s;
        g_a[t] = a;
        out[(size_t)NN * HD + t] = a;
    }
}

// ---------------- final combine ----------------
__global__ void k_final(float* __restrict__ out) {
    int idx = blockIdx.x * blockDim.x + threadIdx.x;
    const int TOT4 = NN * HD / 4;
    if (idx >= TOT4) return;
    float a0 = __ldg(&g_a[0]), a1 = __ldg(&g_a[1]), a2 = __ldg(&g_a[2]);
    const float4* z = (const float4*)g_z;
    float4 z0 = z[idx], z1 = z[idx + TOT4], z2 = z[idx + 2 * TOT4];
    float4 o;
    o.x = a0 * z0.x + a1 * z1.x + a2 * z2.x;
    o.y = a0 * z0.y + a1 * z1.y + a2 * z2.y;
    o.z = a0 * z0.z + a1 * z1.z + a2 * z2.z;
    o.w = a0 * z0.w + a1 * z1.w + a2 * z2.w;
    ((float4*)out)[idx] = o;
}

// ---------------- launch ----------------
extern "C" void kernel_launch(void* const* d_in, const int* in_sizes, int n_in,
                              void* d_out, int out_size) {
    const float* dst_feat  = (const float*)d_in[0];
    const float* src_feats = (const float*)d_in[1];
    const int*   src_idx   = (const int*)d_in[2];
    const int*   dst_idx   = (const int*)d_in[3];
    const float* Wt_dst    = (const float*)d_in[4];
    const float* bt_dst    = (const float*)d_in[5];
    const float* Wt_src    = (const float*)d_in[6];
    const float* bt_src    = (const float*)d_in[7];
    const float* Wg        = (const float*)d_in[8];
    const float* attn_l    = (const float*)d_in[9];
    const float* attn_r    = (const float*)d_in[10];
    const float* bias_g    = (const float*)d_in[11];
    const float* W1        = (const float*)d_in[12];
    const float* b1        = (const float*)d_in[13];
    const float* W2        = (const float*)d_in[14];
    float* out = (float*)d_out;

    size_t smem_mma = (size_t)SMEM_FLOATS * sizeof(float);
    cudaFuncSetAttribute(k_gemm_hs_mma, cudaFuncAttributeMaxDynamicSharedMemorySize, (int)smem_mma);
    cudaFuncSetAttribute(k_semantic_mma, cudaFuncAttributeMaxDynamicSharedMemorySize, (int)smem_mma);

    int eth = RR * EE;
    k_zero<<<(NTOT + 255) / 256, 256>>>();
    k_combine<<<RR * (HIDD + 1), HIDD>>>(Wt_src, bt_src, Wg);
    k_w1t<<<(HD * 128 + 255) / 256, 256>>>(W1);
    k_u<<<(RR * HIDD * HH + 127) / 128, 128>>>(Wg, attn_r);
    k_V<<<(RR * HIDD * HH + 127) / 128, 128>>>(Wt_dst, bt_dst);

    // CSR build (scan3 folded into fill/gather via g_bsum add)
    k_hist<<<(eth + 255) / 256, 256>>>(dst_idx);
    k_scan1<<<(NTOT + 1023) / 1024, 256>>>();
    k_scan2<<<1, 512>>>();
    k_fill<<<(eth + 255) / 256, 256>>>(src_idx, dst_idx);

    dim3 ggrid((NN + 127) / 128, RR);
    k_gemm_hs_mma<<<ggrid, 256, smem_mma>>>(src_feats, attn_l);
    k_er<<<(NN + 7) / 8, 256>>>(dst_feat);

    k_gather<<<(NTOT * 32 + 255) / 256, 256>>>(bias_g);

    k_semantic_mma<<<ggrid, 256, smem_mma>>>(b1, W2);
    k_softmax<<<1, 32>>>(out);
    k_final<<<(NN * HD / 4 + 255) / 256, 256>>>(out);
}